// round 16
// baseline (speedup 1.0000x reference)
#include <cuda_runtime.h>
#include <math.h>

#define HIDDEN   256
#define MAXLEN   256
#define NLAYERS  4
#define VOCAB    50257

// ---------------- scratch (device globals) ---------------------------------
__device__ int   g_c[8];            // 0=B1 attn, 1=B2 applied+embed, 2=BX0 comb, 3=BGH, 4..7=Bgi[l]
__device__ int   g_ct;              // tail barrier counter
__device__ float g_attnlog[MAXLEN];
__device__ float g_cin[2 * HIDDEN]; // [embedded | attn_applied]
__device__ float g_x[HIDDEN];       // comb output (GRU layer-0 input)
__device__ float g_xf[HIDDEN];      // final GRU output (logits input)
__device__ float g_gh[NLAYERS * 3 * HIDDEN];
__device__ float g_gi[NLAYERS * 3 * HIDDEN];
__device__ float g_part[64];

__device__ __forceinline__ float warp_sum(float s) {
#pragma unroll
    for (int o = 16; o; o >>= 1) s += __shfl_down_sync(0xffffffffu, s, o);
    return s;
}
__device__ __forceinline__ float dot4(float4 a, float4 b) {
    return a.x * b.x + a.y * b.y + a.z * b.z + a.w * b.w;
}
__device__ __forceinline__ void bar_spin(int* c, int target) {
    while (*((volatile int*)c) < target) { }
}

// ======================= MEGA KERNEL (417 blocks x 256) =====================
// blocks 0..31  : attn logits -> softmax -> applied -> comb -> GRU (32-arrival barriers)
// block  32     : embed + g_ct reset, then gh
// blocks 33..95 : gh (gh group = blocks 32..95, 64 arrivals)
// blocks 96..416: prefetch out_w/out_b into L2, no barriers
__global__ void __launch_bounds__(256) k_mega(
    const int* __restrict__ token,  const float* __restrict__ hidden,
    const float* __restrict__ enc,  const float* __restrict__ emb,
    const float* __restrict__ attn_w, const float* __restrict__ attn_b,
    const float* __restrict__ comb_w, const float* __restrict__ comb_b,
    const float* __restrict__ wih,  const float* __restrict__ whh,
    const float* __restrict__ bih,  const float* __restrict__ bhh,
    const float* __restrict__ out_w, const float* __restrict__ out_b,
    float* __restrict__ out_attnw,  float* __restrict__ out_hidden)
{
    __shared__ float sh[2 * HIDDEN];
    const int blk = blockIdx.x, tid = threadIdx.x;
    const int w = tid >> 5, lane = tid & 31;

    if (blk >= 96) {
        // ---------------- L2 prefetch of out_w (+ out_b) -------------------
        const int P = 321 * 256;
        int t = (blk - 96) * 256 + tid;
        const float4* W4 = (const float4*)out_w;
        const int NV4 = (VOCAB * HIDDEN) / 4;      // 3,216,448
        float s = 0.f;
        for (int i = t; i < NV4; i += P) {
            float4 v = __ldcg(&W4[i]);
            s += v.x + v.y + v.z + v.w;
        }
        for (int i = t; i < VOCAB; i += P) s += __ldcg(&out_b[i]);
        asm volatile("" :: "f"(s));                // keep the loads
        return;
    }

    if (blk >= 32) {
        // ---------------- gh group: blocks 32..95 (512 warps) --------------
        if (blk == 32) {
            if (tid == 0) g_ct = 0;                 // reset tail counter for next replay
            int tok = token[0];
            float e = __ldg(&emb[(size_t)tok * HIDDEN + tid]);
            __stcg(&g_cin[tid], e);
            __threadfence();
            __syncthreads();
            if (tid == 0) atomicAdd(&g_c[1], 1);    // B2 embed arrival
        }
        int gwid = (blk - 32) * 8 + w;              // 0..511
#pragma unroll
        for (int j = 0; j < 6; j++) {
            int row = gwid + j * 512;               // 0..3071
            int l = row / (3 * HIDDEN), rr = row % (3 * HIDDEN);
            const float4* W = (const float4*)(whh + ((size_t)l * 3 * HIDDEN + rr) * HIDDEN);
            const float4* V = (const float4*)(hidden + l * HIDDEN);
            float s = dot4(__ldg(&W[lane]), __ldg(&V[lane]))
                    + dot4(__ldg(&W[lane + 32]), __ldg(&V[lane + 32]));
            s = warp_sum(s);
            if (lane == 0) __stcg(&g_gh[row], s + __ldg(&bhh[l * 3 * HIDDEN + rr]));
        }
        __threadfence();
        __syncthreads();
        if (tid == 0) atomicAdd(&g_c[3], 1);        // BGH arrival (target 64)
        if (blk >= 96) return;
        return;
    }

    // ==================== blocks 0..31: attention front-end =================
    {
        int row = blk * 8 + w;                      // 0..255
        int tok = token[0];
        const float4* W = (const float4*)(attn_w + (size_t)row * 2 * HIDDEN);
        float s = 0.f;
#pragma unroll
        for (int c = 0; c < 4; c++) {
            float4 a = __ldg(&W[lane + c * 32]);
            int base = (lane + c * 32) * 4;
            float4 v = (base < HIDDEN)
                ? __ldg((const float4*)&emb[(size_t)tok * HIDDEN + base])
                : __ldg((const float4*)&hidden[base - HIDDEN]);
            s += dot4(a, v);
        }
        s = warp_sum(s);
        if (lane == 0) __stcg(&g_attnlog[row], s + __ldg(&attn_b[row]));
    }
    __threadfence();
    __syncthreads();
    if (tid == 0) { atomicAdd(&g_c[0], 1); bar_spin(&g_c[0], 32); }
    __syncthreads();
    __threadfence();

    // ---- softmax (redundant per block) ----
    {
        float v = __ldcg(&g_attnlog[tid]);
        sh[tid] = v; __syncthreads();
        for (int s2 = 128; s2; s2 >>= 1) {
            if (tid < s2) sh[tid] = fmaxf(sh[tid], sh[tid + s2]);
            __syncthreads();
        }
        float m = sh[0]; __syncthreads();
        float e = expf(v - m);
        sh[tid] = e; __syncthreads();
        for (int s2 = 128; s2; s2 >>= 1) {
            if (tid < s2) sh[tid] += sh[tid + s2];
            __syncthreads();
        }
        float wgt = e / sh[0]; __syncthreads();
        sh[HIDDEN + tid] = wgt;
        if (blk == 0) out_attnw[tid] = wgt;
        __syncthreads();
    }

    // ---- attn_applied for t = blk*8 + w ----
    {
        int t = blk * 8 + w;
        float a = 0.f;
#pragma unroll
        for (int j = 0; j < 8; j++) {
            int l2 = lane + j * 32;
            a += sh[HIDDEN + l2] * __ldg(&enc[l2 * HIDDEN + t]);
        }
        a = warp_sum(a);
        if (lane == 0) __stcg(&g_cin[HIDDEN + t], a);
    }
    __threadfence();
    __syncthreads();
    if (tid == 0) { atomicAdd(&g_c[1], 1); bar_spin(&g_c[1], 33); }
    __syncthreads();
    __threadfence();

    // ---- comb + relu: row = blk*8 + w ----
    {
        int row = blk * 8 + w;
        const float4* W = (const float4*)(comb_w + (size_t)row * 2 * HIDDEN);
        float s = 0.f;
#pragma unroll
        for (int c = 0; c < 4; c++) {
            float4 a  = __ldg(&W[lane + c * 32]);
            float4 vv = __ldcg((const float4*)&g_cin[(lane + c * 32) * 4]);
            s += dot4(a, vv);
        }
        s = warp_sum(s);
        if (lane == 0) __stcg(&g_x[row], fmaxf(s + __ldg(&comb_b[row]), 0.f));
    }
    __threadfence();
    __syncthreads();
    if (tid == 0) { atomicAdd(&g_c[2], 1); bar_spin(&g_c[2], 32); }
    __syncthreads();
    __threadfence();

    // ==================== GRU: blocks 0..31, 3 gi rows per warp ============
    sh[tid] = __ldcg(&g_x[tid]);
    __syncthreads();

    for (int l = 0; l < NLAYERS; l++) {
#pragma unroll
        for (int j = 0; j < 3; j++) {
            int r = blk * 24 + w * 3 + j;           // 0..767
            const float4* W = (const float4*)(wih + ((size_t)l * 3 * HIDDEN + r) * HIDDEN);
            const float4* V = (const float4*)sh;
            float s = dot4(__ldg(&W[lane]), V[lane])
                    + dot4(__ldg(&W[lane + 32]), V[lane + 32]);
            s = warp_sum(s);
            if (lane == 0) __stcg(&g_gi[l * 3 * HIDDEN + r], s + __ldg(&bih[l * 3 * HIDDEN + r]));
        }
        __threadfence();
        __syncthreads();
        if (tid == 0) {
            atomicAdd(&g_c[4 + l], 1);
            if (l == 0) bar_spin(&g_c[3], 64);      // gh complete
            bar_spin(&g_c[4 + l], 32);
        }
        __syncthreads();
        __threadfence();

        const float* gi = g_gi + l * 3 * HIDDEN;
        const float* gh = g_gh + l * 3 * HIDDEN;
        float ir = __ldcg(&gi[tid]),  iz = __ldcg(&gi[HIDDEN + tid]),  in_ = __ldcg(&gi[2 * HIDDEN + tid]);
        float hr = __ldcg(&gh[tid]),  hz = __ldcg(&gh[HIDDEN + tid]),  hn  = __ldcg(&gh[2 * HIDDEN + tid]);
        float rg = 1.f / (1.f + expf(-(ir + hr)));
        float zg = 1.f / (1.f + expf(-(iz + hz)));
        float ng = tanhf(in_ + rg * hn);
        float hp = __ldg(&hidden[l * HIDDEN + tid]);
        float h  = (1.f - zg) * ng + zg * hp;
        __syncthreads();
        sh[tid] = h;
        if (blk == 0) out_hidden[l * HIDDEN + tid] = h;
        __syncthreads();
    }
    if (blk == 0) __stcg(&g_xf[tid], sh[tid]);
}

// ======================= vocab logits: 4 rows per warp ======================
__global__ void __launch_bounds__(256) k_logits(
    const float* __restrict__ out_w, const float* __restrict__ out_b,
    float* __restrict__ logits)
{
    __shared__ float sx[HIDDEN];
    int tid = threadIdx.x, w = tid >> 5, lane = tid & 31;
    sx[tid] = __ldcg(&g_xf[tid]);
    __syncthreads();
    const float4* V = (const float4*)sx;
    float4 v0 = V[lane], v1 = V[lane + 32];
    int r0 = (blockIdx.x * 8 + w) * 4;
    float s0 = 0.f, s1 = 0.f, s2 = 0.f, s3 = 0.f;
    if (r0 + 0 < VOCAB) { const float4* W = (const float4*)(out_w + (size_t)(r0 + 0) * HIDDEN); s0 = dot4(__ldg(&W[lane]), v0) + dot4(__ldg(&W[lane + 32]), v1); }
    if (r0 + 1 < VOCAB) { const float4* W = (const float4*)(out_w + (size_t)(r0 + 1) * HIDDEN); s1 = dot4(__ldg(&W[lane]), v0) + dot4(__ldg(&W[lane + 32]), v1); }
    if (r0 + 2 < VOCAB) { const float4* W = (const float4*)(out_w + (size_t)(r0 + 2) * HIDDEN); s2 = dot4(__ldg(&W[lane]), v0) + dot4(__ldg(&W[lane + 32]), v1); }
    if (r0 + 3 < VOCAB) { const float4* W = (const float4*)(out_w + (size_t)(r0 + 3) * HIDDEN); s3 = dot4(__ldg(&W[lane]), v0) + dot4(__ldg(&W[lane + 32]), v1); }
#pragma unroll
    for (int o = 16; o; o >>= 1) {
        s0 += __shfl_down_sync(0xffffffffu, s0, o);
        s1 += __shfl_down_sync(0xffffffffu, s1, o);
        s2 += __shfl_down_sync(0xffffffffu, s2, o);
        s3 += __shfl_down_sync(0xffffffffu, s3, o);
    }
    if (lane == 0) {
        if (r0 + 0 < VOCAB) logits[r0 + 0] = s0 + __ldg(&out_b[r0 + 0]);
        if (r0 + 1 < VOCAB) logits[r0 + 1] = s1 + __ldg(&out_b[r0 + 1]);
        if (r0 + 2 < VOCAB) logits[r0 + 2] = s2 + __ldg(&out_b[r0 + 2]);
        if (r0 + 3 < VOCAB) logits[r0 + 3] = s3 + __ldg(&out_b[r0 + 3]);
    }
}

// ============== fused log-softmax tail (64 blocks, 1 barrier) ===============
__global__ void __launch_bounds__(256) k_tail(float* __restrict__ logits)
{
    __shared__ float red[256];
    int tid = threadIdx.x, blk = blockIdx.x;
    float s = 0.f;
    for (int i = blk * 256 + tid; i < VOCAB; i += 64 * 256) s += expf(logits[i]);
    red[tid] = s; __syncthreads();
    for (int st = 128; st; st >>= 1) {
        if (tid < st) red[tid] += red[tid + st];
        __syncthreads();
    }
    if (tid == 0) {
        __stcg(&g_part[blk], red[0]);
        __threadfence();
        atomicAdd(&g_ct, 1);
        bar_spin(&g_ct, 64);
        __threadfence();
        float tot = 0.f;
        for (int i = 0; i < 64; i++) tot += __ldcg(&g_part[i]);
        red[0] = logf(tot);
    }
    __syncthreads();
    float lse = red[0];
    for (int i = blk * 256 + tid; i < VOCAB; i += 64 * 256) logits[i] -= lse;
    if (blk == 0 && tid == 0) {
#pragma unroll
        for (int i = 0; i < 8; i++) g_c[i] = 0;     // reset mega barriers for next replay
    }
}

// ---------------------------------------------------------------------------
extern "C" void kernel_launch(void* const* d_in, const int* in_sizes, int n_in,
                              void* d_out, int out_size) {
    const int*   token  = (const int*)  d_in[0];
    const float* hidden = (const float*)d_in[1];
    const float* enc    = (const float*)d_in[2];
    const float* emb    = (const float*)d_in[3];
    const float* attn_w = (const float*)d_in[4];
    const float* attn_b = (const float*)d_in[5];
    const float* comb_w = (const float*)d_in[6];
    const float* comb_b = (const float*)d_in[7];
    const float* g_wih  = (const float*)d_in[8];
    const float* g_whh  = (const float*)d_in[9];
    const float* g_bih  = (const float*)d_in[10];
    const float* g_bhh  = (const float*)d_in[11];
    const float* out_w  = (const float*)d_in[12];
    const float* out_b  = (const float*)d_in[13];

    float* out        = (float*)d_out;
    float* out_logits = out;
    float* out_hidden = out + VOCAB;
    float* out_attnw  = out + VOCAB + NLAYERS * HIDDEN;

    k_mega<<<417, 256>>>(token, hidden, enc, emb, attn_w, attn_b, comb_w, comb_b,
                         g_wih, g_whh, g_bih, g_bhh, out_w, out_b,
                         out_attnw, out_hidden);
    k_logits<<<(VOCAB + 31) / 32, 256>>>(out_w, out_b, out_logits);
    k_tail<<<64, 256>>>(out_logits);
}